// round 2
// baseline (speedup 1.0000x reference)
#include <cuda_runtime.h>
#include <math.h>

// Problem constants
constexpr int NUM_C = 100;
constexpr int NUM_D = 384;
constexpr int NUM_B = 4096;

constexpr int DQ = NUM_D / 4;       // 96 float4 quads per row
constexpr int ROWS2 = 32;           // rows per block in k_main
constexpr int GRID2 = NUM_B / ROWS2; // 128 blocks
constexpr int NW2 = 8;              // warps per block
constexpr int T2 = NW2 * 32;        // 256 threads
constexpr int NC = 5;               // classes per chunk
constexpr int NCHUNK = NUM_C / NC;  // 20 chunks
constexpr int SX_STRIDE = 33;       // float4 stride (bank-conflict-free)

// Scratch (device globals; no allocation allowed)
__device__ float g_A[NUM_C * NUM_D];    // 2^w
__device__ float g_WC[NUM_C * NUM_D];   // 2^w * center
__device__ float g_tcc[NUM_C];          // sum_d 2^w * c^2
__device__ float g_cdist[NUM_C];        // closest-other-center dist
__device__ int   g_present[NUM_C];      // class appears in targets
__device__ float g_partial[GRID2];      // per-block sums

// ---------------------------------------------------------------------------
// Kernel 1: per-class precompute + centers_dist + present flags
// grid = NUM_C blocks, 128 threads
// ---------------------------------------------------------------------------
__global__ void __launch_bounds__(128) k_setup(const float* __restrict__ centers,
                                               const float* __restrict__ cw,
                                               const int* __restrict__ targets) {
    __shared__ float a_s[NUM_D];
    __shared__ float c_s[NUM_D];
    __shared__ float red[4];
    __shared__ float cd_s[4];

    const int c = blockIdx.x;
    const int tid = threadIdx.x;
    const int lane = tid & 31;
    const int w = tid >> 5;

    // A = 2^w, WC = A*center, tcc = sum A*center^2
    float tcc = 0.f;
    for (int d = tid; d < NUM_D; d += 128) {
        float a = exp2f(cw[c * NUM_D + d]);
        float cen = centers[c * NUM_D + d];
        a_s[d] = a;
        c_s[d] = cen;
        g_A[c * NUM_D + d] = a;
        g_WC[c * NUM_D + d] = a * cen;
        tcc = fmaf(a * cen, cen, tcc);
    }
    #pragma unroll
    for (int o = 16; o; o >>= 1) tcc += __shfl_xor_sync(0xFFFFFFFFu, tcc, o);
    if (lane == 0) red[w] = tcc;
    __syncthreads();
    if (tid == 0) g_tcc[c] = (red[0] + red[1]) + (red[2] + red[3]);

    // centers_dist[c] = min over e != c of sqrt(sum_d 2^w[c,d]*(c[c,d]-c[e,d])^2)
    float dmin = INFINITY;
    for (int e = w; e < NUM_C; e += 4) {
        if (e == c) continue;
        float s = 0.f;
        #pragma unroll
        for (int k = 0; k < NUM_D / 32; k++) {
            int d = lane + k * 32;
            float diff = c_s[d] - centers[e * NUM_D + d];
            s = fmaf(a_s[d] * diff, diff, s);
        }
        #pragma unroll
        for (int o = 16; o; o >>= 1) s += __shfl_xor_sync(0xFFFFFFFFu, s, o);
        dmin = fminf(dmin, sqrtf(s));
    }
    if (lane == 0) cd_s[w] = dmin;

    // present flag: does class c appear in targets?
    int f = 0;
    for (int j = tid; j < NUM_B; j += 128) f |= (targets[j] == c);
    int any = __syncthreads_or(f);   // barrier also publishes cd_s
    if (tid == 0) {
        g_present[c] = any;
        g_cdist[c] = fminf(fminf(cd_s[0], cd_s[1]), fminf(cd_s[2], cd_s[3]));
    }
}

// ---------------------------------------------------------------------------
// Kernel 2: main [B x C] distance pass + hardest-pos/neg + per-block sum
// grid = 128 blocks, 256 threads, dynamic smem for 32 staged rows
// ---------------------------------------------------------------------------
__global__ void __launch_bounds__(T2) k_main(const float* __restrict__ inputs,
                                             const int* __restrict__ targets) {
    extern __shared__ float4 sx[];   // [DQ][32] quad-major, stride 33 (padded)
    __shared__ float s_ap[NW2 * 32];
    __shared__ float s_an[NW2 * 32];

    const int tid = threadIdx.x;
    const int lane = tid & 31;
    const int w = tid >> 5;
    const int row0 = blockIdx.x * ROWS2;

    // Stage 32 rows of inputs, transposed to quad-major [q][row] layout.
    // Coalesced global reads; conflict-free scalar smem writes (stride 132 floats).
    for (int idx = tid; idx < ROWS2 * NUM_D; idx += T2) {
        const int i = idx / NUM_D;
        const int d = idx - i * NUM_D;
        const float v = inputs[(row0 + i) * NUM_D + d];
        reinterpret_cast<float*>(&sx[(d >> 2) * SX_STRIDE + i])[d & 3] = v;
    }
    __syncthreads();

    const int myt = targets[row0 + lane];
    float ap = -INFINITY;
    float an = INFINITY;

    const float4* __restrict__ WC4 = reinterpret_cast<const float4*>(g_WC);
    const float4* __restrict__ A4  = reinterpret_cast<const float4*>(g_A);

    // 20 chunks of 5 classes; warps 0-3 take 3 chunks, 4-7 take 2 ->
    // exactly 25 classes per SMSP (warps w and w+4 pair), FMA-balanced.
    for (int chunk = w; chunk < NCHUNK; chunk += NW2) {
        const int c0 = chunk * NC;
        float axc[NC], axx[NC];
        #pragma unroll
        for (int k = 0; k < NC; k++) { axc[k] = 0.f; axx[k] = 0.f; }

        const float4* __restrict__ wp  = WC4 + c0 * DQ;
        const float4* __restrict__ apr = A4  + c0 * DQ;

        #pragma unroll 2
        for (int q = 0; q < DQ; q++) {
            const float4 xv = sx[q * SX_STRIDE + lane];  // conflict-free LDS.128
            float4 x2;
            x2.x = xv.x * xv.x; x2.y = xv.y * xv.y;
            x2.z = xv.z * xv.z; x2.w = xv.w * xv.w;
            #pragma unroll
            for (int k = 0; k < NC; k++) {
                const float4 wc = __ldg(&wp[k * DQ + q]);   // broadcast LDG.128, L1-hot
                const float4 av = __ldg(&apr[k * DQ + q]);
                axc[k] = fmaf(xv.x, wc.x, axc[k]);
                axc[k] = fmaf(xv.y, wc.y, axc[k]);
                axc[k] = fmaf(xv.z, wc.z, axc[k]);
                axc[k] = fmaf(xv.w, wc.w, axc[k]);
                axx[k] = fmaf(x2.x, av.x, axx[k]);
                axx[k] = fmaf(x2.y, av.y, axx[k]);
                axx[k] = fmaf(x2.z, av.z, axx[k]);
                axx[k] = fmaf(x2.w, av.w, axx[k]);
            }
        }

        #pragma unroll
        for (int k = 0; k < NC; k++) {
            const int c = c0 + k;
            const float d2 = g_tcc[c] - 2.f * axc[k] + axx[k];
            const float dist = sqrtf(fmaxf(d2, 1e-12f));
            if (c == myt) {
                ap = fmaxf(ap, dist);
            } else if (g_present[c]) {
                an = fminf(an, dist);
            }
        }
    }

    // Cross-warp reduce per row (lane == row)
    s_ap[w * 32 + lane] = ap;
    s_an[w * 32 + lane] = an;
    __syncthreads();
    if (w == 0) {
        float AP = s_ap[lane];
        float AN = s_an[lane];
        #pragma unroll
        for (int ww = 1; ww < NW2; ww++) {
            AP = fmaxf(AP, s_ap[ww * 32 + lane]);
            AN = fminf(AN, s_an[ww * 32 + lane]);
        }
        const float cc = g_cdist[myt];
        float per = AP + fmaxf(0.f, cc - AN);  // where(an >= cc, 0, cc - an)
        #pragma unroll
        for (int o = 16; o; o >>= 1) per += __shfl_xor_sync(0xFFFFFFFFu, per, o);
        if (lane == 0) g_partial[blockIdx.x] = per;
    }
}

// ---------------------------------------------------------------------------
// Kernel 3: deterministic fixed-order final reduction
// ---------------------------------------------------------------------------
__global__ void __launch_bounds__(128) k_final(float* __restrict__ out) {
    __shared__ float r[4];
    const int tid = threadIdx.x;
    float v = g_partial[tid];
    #pragma unroll
    for (int o = 16; o; o >>= 1) v += __shfl_xor_sync(0xFFFFFFFFu, v, o);
    if ((tid & 31) == 0) r[tid >> 5] = v;
    __syncthreads();
    if (tid == 0) out[0] = ((r[0] + r[1]) + (r[2] + r[3])) * (1.0f / (float)NUM_B);
}

// ---------------------------------------------------------------------------
extern "C" void kernel_launch(void* const* d_in, const int* in_sizes, int n_in,
                              void* d_out, int out_size) {
    (void)in_sizes; (void)n_in; (void)out_size;
    const float* inputs  = (const float*)d_in[0];   // [4096, 384] f32
    const int*   targets = (const int*)d_in[1];     // [4096] i32
    // d_in[2] = epoch_number (unused)
    const float* centers = (const float*)d_in[3];   // [100, 384] f32
    const float* cw      = (const float*)d_in[4];   // [100, 384] f32
    float* out = (float*)d_out;

    const int smem2 = DQ * SX_STRIDE * (int)sizeof(float4);  // 50688 B
    cudaFuncSetAttribute(k_main, cudaFuncAttributeMaxDynamicSharedMemorySize, smem2);

    k_setup<<<NUM_C, 128>>>(centers, cw, targets);
    k_main<<<GRID2, T2, smem2>>>(inputs, targets);
    k_final<<<1, 128>>>(out);
}

// round 6
// speedup vs baseline: 1.7335x; 1.7335x over previous
#include <cuda_runtime.h>
#include <math.h>

// Problem constants
constexpr int NUM_C = 100;
constexpr int NUM_D = 384;
constexpr int NUM_B = 4096;

constexpr int ROWS2 = 32;             // rows per k_main block
constexpr int GRID2 = NUM_B / ROWS2;  // 128 blocks
constexpr int T2 = 256;               // 8 warps
constexpr int SX_STRIDE = 33;         // float4 stride, conflict-free
constexpr int CHUNK_D = 48;           // dims per class-chunk stage
constexpr int NCHUNKS = NUM_D / CHUNK_D;   // 8
constexpr int QPC = CHUNK_D / 4;      // 12 quads per class per chunk
constexpr int CEN_STRIDE = 385;       // setup centers smem stride (floats)

typedef unsigned long long u64;

// Scratch (device globals; no allocation allowed)
__device__ float g_A[NUM_C * NUM_D];    // 2^w
__device__ float g_WC[NUM_C * NUM_D];   // 2^w * center
__device__ float g_tcc[NUM_C];          // sum_d 2^w * c^2
__device__ float g_cdist[NUM_C];        // closest-other-center dist
__device__ int   g_present[NUM_C];      // class appears in targets
__device__ float g_partial[GRID2];      // per-block sums

// ---- packed f32x2 helpers (SASS FFMA2 path; PTX-only per sm_10x) ----------
__device__ __forceinline__ u64 f32x2_mul(u64 a, u64 b) {
    u64 r; asm("mul.rn.f32x2 %0, %1, %2;" : "=l"(r) : "l"(a), "l"(b)); return r;
}
__device__ __forceinline__ u64 f32x2_fma(u64 a, u64 b, u64 c) {
    u64 r; asm("fma.rn.f32x2 %0, %1, %2, %3;" : "=l"(r) : "l"(a), "l"(b), "l"(c)); return r;
}
__device__ __forceinline__ float2 f32x2_unpack(u64 v) {
    float2 r; asm("mov.b64 {%0, %1}, %2;" : "=f"(r.x), "=f"(r.y) : "l"(v)); return r;
}

// ---------------------------------------------------------------------------
// Kernel 1: per-class precompute (A, WC, tcc), centers_dist, present flags.
// grid = 100 blocks x 128 threads; all centers staged in smem (stride 385).
// ---------------------------------------------------------------------------
__global__ void __launch_bounds__(128) k_setup(const float* __restrict__ centers,
                                               const float* __restrict__ cw,
                                               const int* __restrict__ targets) {
    extern __shared__ float cen_s[];     // [100][385]
    __shared__ float a_s[NUM_D];
    __shared__ float c_s[NUM_D];
    __shared__ float red[4];
    __shared__ int s_min;

    const int c = blockIdx.x;
    const int tid = threadIdx.x;
    const int lane = tid & 31;
    const int w = tid >> 5;

    // Part 1: A = 2^w, WC = A*center, tcc = sum A*c^2, fill a_s/c_s
    float tcc = 0.f;
    for (int d = tid; d < NUM_D; d += 128) {
        float a = exp2f(cw[c * NUM_D + d]);
        float cen = centers[c * NUM_D + d];
        a_s[d] = a;
        c_s[d] = cen;
        g_A[c * NUM_D + d] = a;
        g_WC[c * NUM_D + d] = a * cen;
        tcc = fmaf(a * cen, cen, tcc);
    }
    #pragma unroll
    for (int o = 16; o; o >>= 1) tcc += __shfl_xor_sync(0xFFFFFFFFu, tcc, o);
    if (lane == 0) red[w] = tcc;

    // Part 2: stage ALL centers into smem (coalesced f4 loads, scalar stores)
    for (int i = tid * 4; i < NUM_C * NUM_D; i += 128 * 4) {
        const int e = i / NUM_D;
        const int d = i - e * NUM_D;
        const float4 v = *reinterpret_cast<const float4*>(centers + i);
        float* dst = cen_s + e * CEN_STRIDE + d;
        dst[0] = v.x; dst[1] = v.y; dst[2] = v.z; dst[3] = v.w;
    }
    if (tid == 0) s_min = 0x7f7fffff;   // +FLT_MAX bits
    __syncthreads();

    if (tid == 0) g_tcc[c] = (red[0] + red[1]) + (red[2] + red[3]);

    // Part 3: cdist — thread t owns class e=t; conflict-free stride-385 reads
    if (tid < NUM_C && tid != c) {
        const float* cr = cen_s + tid * CEN_STRIDE;
        float s0 = 0.f, s1 = 0.f, s2 = 0.f, s3 = 0.f;
        #pragma unroll 4
        for (int d = 0; d < NUM_D; d += 4) {
            float t0 = c_s[d + 0] - cr[d + 0]; s0 = fmaf(a_s[d + 0] * t0, t0, s0);
            float t1 = c_s[d + 1] - cr[d + 1]; s1 = fmaf(a_s[d + 1] * t1, t1, s1);
            float t2 = c_s[d + 2] - cr[d + 2]; s2 = fmaf(a_s[d + 2] * t2, t2, s2);
            float t3 = c_s[d + 3] - cr[d + 3]; s3 = fmaf(a_s[d + 3] * t3, t3, s3);
        }
        const float s = (s0 + s1) + (s2 + s3);
        atomicMin(&s_min, __float_as_int(sqrtf(s)));  // positive floats: int order ok
    }

    // Part 4: present flag (coalesced scan; targets is 16KB, L2-hot)
    int f = 0;
    for (int j = tid; j < NUM_B; j += 128) f |= (targets[j] == c);
    const int any = __syncthreads_or(f);   // barrier also publishes s_min
    if (tid == 0) {
        g_present[c] = any;
        g_cdist[c] = __int_as_float(s_min);
    }
}

// ---------------------------------------------------------------------------
// k_main inner: accumulate one 48-dim chunk for KN classes (packed f32x2)
// ---------------------------------------------------------------------------
template <int KN>
__device__ __forceinline__ void chunk_accum(const float4* __restrict__ sxb,
                                            const float4* __restrict__ cls,
                                            int c0, int lane,
                                            u64* __restrict__ axc,
                                            u64* __restrict__ axx) {
    #pragma unroll
    for (int qi = 0; qi < QPC; qi++) {
        const ulonglong2 xq =
            *reinterpret_cast<const ulonglong2*>(&sxb[qi * SX_STRIDE + lane]);
        const u64 x2lo = f32x2_mul(xq.x, xq.x);
        const u64 x2hi = f32x2_mul(xq.y, xq.y);
        #pragma unroll
        for (int k = 0; k < KN; k++) {
            const float4* p = cls + (c0 + k) * (2 * QPC) + 2 * qi;
            const ulonglong2 wc = *reinterpret_cast<const ulonglong2*>(p);
            const ulonglong2 av = *reinterpret_cast<const ulonglong2*>(p + 1);
            axc[k] = f32x2_fma(xq.x, wc.x, axc[k]);
            axc[k] = f32x2_fma(xq.y, wc.y, axc[k]);
            axx[k] = f32x2_fma(x2lo, av.x, axx[k]);
            axx[k] = f32x2_fma(x2hi, av.y, axx[k]);
        }
    }
}

// ---------------------------------------------------------------------------
// Kernel 2: [B x C] distance pass. 32 rows/block (lane=row), 8 warps,
// warps 0-3 own 13 classes, warps 4-7 own 12. Class data smem-staged per
// 48-dim chunk; packed f32x2 FMAs.
// ---------------------------------------------------------------------------
__global__ void __launch_bounds__(T2) k_main(const float* __restrict__ inputs,
                                             const int* __restrict__ targets) {
    extern __shared__ float4 dynsm[];
    float4* sx4 = dynsm;                               // [96][33] quad-major x
    float4* cls = dynsm + 96 * SX_STRIDE;              // [100][24] {WC,A} quads
    float* s_ap = reinterpret_cast<float*>(cls + NUM_C * 2 * QPC);
    float* s_an = s_ap + T2;

    const int tid = threadIdx.x;
    const int lane = tid & 31;
    const int w = tid >> 5;
    const int row0 = blockIdx.x * ROWS2;

    // Stage 32 input rows, transposed to quad-major [q][row] (coalesced LDG.128)
    {
        const float4* in4 = reinterpret_cast<const float4*>(inputs) + row0 * (NUM_D / 4);
        for (int i = tid; i < ROWS2 * (NUM_D / 4); i += T2) {
            const int r = i / (NUM_D / 4);
            const int q = i - r * (NUM_D / 4);
            sx4[q * SX_STRIDE + r] = in4[i];
        }
    }

    const int myt = targets[row0 + lane];
    const int c0 = (w < 4) ? w * 13 : 52 + (w - 4) * 12;
    const int cnt = (w < 4) ? 13 : 12;

    u64 axc[13], axx[13];
    #pragma unroll
    for (int k = 0; k < 13; k++) { axc[k] = 0ull; axx[k] = 0ull; }

    const float4* __restrict__ WC4 = reinterpret_cast<const float4*>(g_WC);
    const float4* __restrict__ A4 = reinterpret_cast<const float4*>(g_A);

    for (int s = 0; s < NCHUNKS; s++) {
        __syncthreads();   // previous chunk fully consumed (also covers x-stage)
        // Stage chunk s of {WC, A}, interleaved per class: [c][2*qi]=WC, [c][2*qi+1]=A
        for (int i = tid; i < NUM_C * QPC; i += T2) {
            const int c = i / QPC;
            const int qi = i - c * QPC;
            const int src = c * (NUM_D / 4) + s * QPC + qi;
            cls[c * (2 * QPC) + 2 * qi] = WC4[src];
            cls[c * (2 * QPC) + 2 * qi + 1] = A4[src];
        }
        __syncthreads();

        const float4* sxb = sx4 + s * QPC * SX_STRIDE;
        if (w < 4) chunk_accum<13>(sxb, cls, c0, lane, axc, axx);
        else       chunk_accum<12>(sxb, cls, c0, lane, axc, axx);
    }

    // Epilogue: distances + hardest pos/neg over this warp's classes
    float ap = -INFINITY, an = INFINITY;
    for (int k = 0; k < cnt; k++) {
        const int c = c0 + k;
        const float2 pc = f32x2_unpack(axc[k]);
        const float2 px = f32x2_unpack(axx[k]);
        const float axcv = pc.x + pc.y;
        const float axxv = px.x + px.y;
        const float d2 = g_tcc[c] - 2.f * axcv + axxv;
        const float dist = sqrtf(fmaxf(d2, 1e-12f));
        if (c == myt) ap = fmaxf(ap, dist);
        else if (g_present[c]) an = fminf(an, dist);
    }

    // Cross-warp reduce per row (lane == row)
    s_ap[w * 32 + lane] = ap;
    s_an[w * 32 + lane] = an;
    __syncthreads();
    if (w == 0) {
        float AP = s_ap[lane];
        float AN = s_an[lane];
        #pragma unroll
        for (int ww = 1; ww < 8; ww++) {
            AP = fmaxf(AP, s_ap[ww * 32 + lane]);
            AN = fminf(AN, s_an[ww * 32 + lane]);
        }
        const float cc = g_cdist[myt];
        float per = AP + fmaxf(0.f, cc - AN);
        #pragma unroll
        for (int o = 16; o; o >>= 1) per += __shfl_xor_sync(0xFFFFFFFFu, per, o);
        if (lane == 0) g_partial[blockIdx.x] = per;
    }
}

// ---------------------------------------------------------------------------
// Kernel 3: deterministic fixed-order final reduction
// ---------------------------------------------------------------------------
__global__ void __launch_bounds__(128) k_final(float* __restrict__ out) {
    __shared__ float r[4];
    const int tid = threadIdx.x;
    float v = g_partial[tid];
    #pragma unroll
    for (int o = 16; o; o >>= 1) v += __shfl_xor_sync(0xFFFFFFFFu, v, o);
    if ((tid & 31) == 0) r[tid >> 5] = v;
    __syncthreads();
    if (tid == 0) out[0] = ((r[0] + r[1]) + (r[2] + r[3])) * (1.0f / (float)NUM_B);
}

// ---------------------------------------------------------------------------
extern "C" void kernel_launch(void* const* d_in, const int* in_sizes, int n_in,
                              void* d_out, int out_size) {
    (void)in_sizes; (void)n_in; (void)out_size;
    const float* inputs  = (const float*)d_in[0];   // [4096, 384] f32
    const int*   targets = (const int*)d_in[1];     // [4096] i32
    // d_in[2] = epoch_number (unused)
    const float* centers = (const float*)d_in[3];   // [100, 384] f32
    const float* cw      = (const float*)d_in[4];   // [100, 384] f32
    float* out = (float*)d_out;

    const int smem_setup = NUM_C * CEN_STRIDE * (int)sizeof(float);              // 154000
    const int smem_main = (96 * SX_STRIDE + NUM_C * 2 * QPC) * (int)sizeof(float4)
                          + 2 * T2 * (int)sizeof(float);                         // 91136
    cudaFuncSetAttribute(k_setup, cudaFuncAttributeMaxDynamicSharedMemorySize, smem_setup);
    cudaFuncSetAttribute(k_main, cudaFuncAttributeMaxDynamicSharedMemorySize, smem_main);

    k_setup<<<NUM_C, 128, smem_setup>>>(centers, cw, targets);
    k_main<<<GRID2, T2, smem_main>>>(inputs, targets);
    k_final<<<1, 128>>>(out);
}

// round 9
// speedup vs baseline: 1.8479x; 1.0660x over previous
#include <cuda_runtime.h>
#include <math.h>

// Problem constants
constexpr int NUM_C = 100;
constexpr int NUM_D = 384;
constexpr int NUM_B = 4096;

constexpr int ROWS = 16;                  // rows per k_main block
constexpr int GRID2 = NUM_B / ROWS;       // 256 blocks
constexpr int T2 = 256;                   // 8 warps
constexpr int SXS = 17;                   // sx float4 stride (conflict-free)
constexpr int QPC = 12;                   // quads per class per chunk (48 dims)
constexpr int NCHUNKS = 8;                // 8 * 48 = 384
constexpr int CEN_STRIDE = 385;           // setup centers smem stride (floats)

typedef unsigned long long u64;

// Scratch (device globals; no allocation allowed)
__device__ float g_A[NUM_C * NUM_D];      // 2^w
__device__ float g_WC[NUM_C * NUM_D];     // 2^w * center
__device__ float g_tcc[NUM_C];            // sum_d 2^w * c^2
__device__ float g_cdist[NUM_C];          // closest-other-center dist
__device__ int   g_present[NUM_C];        // class appears in targets
__device__ float g_partial[GRID2];        // per-block sums
__device__ int   g_count = 0;             // last-block counter (reset each run)

// ---- packed f32x2 helpers (SASS FFMA2 path; PTX-only) ---------------------
__device__ __forceinline__ u64 f32x2_mul(u64 a, u64 b) {
    u64 r; asm("mul.rn.f32x2 %0, %1, %2;" : "=l"(r) : "l"(a), "l"(b)); return r;
}
__device__ __forceinline__ u64 f32x2_fma(u64 a, u64 b, u64 c) {
    u64 r; asm("fma.rn.f32x2 %0, %1, %2, %3;" : "=l"(r) : "l"(a), "l"(b), "l"(c)); return r;
}
__device__ __forceinline__ float2 f32x2_unpack(u64 v) {
    float2 r; asm("mov.b64 {%0, %1}, %2;" : "=f"(r.x), "=f"(r.y) : "l"(v)); return r;
}

// ---------------------------------------------------------------------------
// Kernel 1: per-class precompute (A, WC, tcc), centers_dist, present flags.
// grid = 100 blocks x 256 threads; all centers staged in smem (stride 385).
// cdist: 200 threads, each owns (class e, 192-dim half); halves combined in smem.
// ---------------------------------------------------------------------------
__global__ void __launch_bounds__(T2) k_setup(const float* __restrict__ centers,
                                              const float* __restrict__ cw,
                                              const int* __restrict__ targets) {
    extern __shared__ float cen_s[];      // [100][385]
    __shared__ float a_s[NUM_D];
    __shared__ float c_s[NUM_D];
    __shared__ float red[8];
    __shared__ float s_half[200];
    __shared__ int s_min;

    const int c = blockIdx.x;
    const int tid = threadIdx.x;
    const int lane = tid & 31;
    const int w = tid >> 5;

    if (tid == 0) s_min = 0x7f7fffff;     // +FLT_MAX bits

    // Stage ALL centers into smem (coalesced f4 loads, scalar stores)
    for (int i = tid * 4; i < NUM_C * NUM_D; i += T2 * 4) {
        const int e = i / NUM_D;
        const int d = i - e * NUM_D;
        const float4 v = *reinterpret_cast<const float4*>(centers + i);
        float* dst = cen_s + e * CEN_STRIDE + d;
        dst[0] = v.x; dst[1] = v.y; dst[2] = v.z; dst[3] = v.w;
    }

    // A = 2^w, WC = A*center, tcc partials (fixed thread->warp order: deterministic)
    float tcc = 0.f;
    for (int d = tid; d < NUM_D; d += T2) {
        const float a = exp2f(cw[c * NUM_D + d]);
        const float cen = centers[c * NUM_D + d];
        a_s[d] = a;
        c_s[d] = cen;
        g_A[c * NUM_D + d] = a;
        g_WC[c * NUM_D + d] = a * cen;
        tcc = fmaf(a * cen, cen, tcc);
    }
    #pragma unroll
    for (int o = 16; o; o >>= 1) tcc += __shfl_xor_sync(0xFFFFFFFFu, tcc, o);
    if (lane == 0) red[w] = tcc;
    __syncthreads();

    if (tid == 0)
        g_tcc[c] = ((red[0] + red[1]) + (red[2] + red[3]))
                 + ((red[4] + red[5]) + (red[6] + red[7]));

    // cdist: thread t<200 owns (e = t%100, half = t/100); 192-dim serial chain
    if (tid < 200) {
        const int half = (tid >= 100);
        const int e = tid - half * 100;
        const int d0 = half * 192;
        const float* cr = cen_s + e * CEN_STRIDE + d0;
        const float* ap = a_s + d0;
        const float* cp = c_s + d0;
        float s0 = 0.f, s1 = 0.f, s2 = 0.f, s3 = 0.f;
        #pragma unroll 4
        for (int d = 0; d < 192; d += 4) {
            float t0 = cp[d + 0] - cr[d + 0]; s0 = fmaf(ap[d + 0] * t0, t0, s0);
            float t1 = cp[d + 1] - cr[d + 1]; s1 = fmaf(ap[d + 1] * t1, t1, s1);
            float t2 = cp[d + 2] - cr[d + 2]; s2 = fmaf(ap[d + 2] * t2, t2, s2);
            float t3 = cp[d + 3] - cr[d + 3]; s3 = fmaf(ap[d + 3] * t3, t3, s3);
        }
        s_half[tid] = (s0 + s1) + (s2 + s3);
    }

    // present flag scan (independent of cdist halves; barrier below covers both)
    int f = 0;
    for (int j = tid; j < NUM_B; j += T2) f |= (targets[j] == c);
    const int any = __syncthreads_or(f);

    if (tid < 100 && tid != c) {
        const float s = s_half[tid] + s_half[100 + tid];
        atomicMin(&s_min, __float_as_int(sqrtf(s)));  // positive floats: int order ok
    }
    __syncthreads();
    if (tid == 0) {
        g_present[c] = any;
        g_cdist[c] = __int_as_float(s_min);
    }
}

// ---------------------------------------------------------------------------
// k_main inner: accumulate one 48-dim chunk for KN classes (packed f32x2).
// myCls already offset to this lane's class group; offsets are compile-time.
// ---------------------------------------------------------------------------
template <int KN>
__device__ __forceinline__ void chunk_accum(const float4* __restrict__ sxb,
                                            const float4* __restrict__ myCls,
                                            int row,
                                            u64* __restrict__ axc,
                                            u64* __restrict__ axx) {
    #pragma unroll
    for (int qi = 0; qi < QPC; qi++) {
        const ulonglong2 xq =
            *reinterpret_cast<const ulonglong2*>(&sxb[qi * SXS + row]);
        const u64 x2lo = f32x2_mul(xq.x, xq.x);
        const u64 x2hi = f32x2_mul(xq.y, xq.y);
        #pragma unroll
        for (int k = 0; k < KN; k++) {
            const float4* p = myCls + k * (2 * QPC) + 2 * qi;
            const ulonglong2 wc = *reinterpret_cast<const ulonglong2*>(p);
            const ulonglong2 av = *reinterpret_cast<const ulonglong2*>(p + 1);
            axc[k] = f32x2_fma(xq.x, wc.x, axc[k]);
            axc[k] = f32x2_fma(xq.y, wc.y, axc[k]);
            axx[k] = f32x2_fma(x2lo, av.x, axx[k]);
            axx[k] = f32x2_fma(x2hi, av.y, axx[k]);
        }
    }
}

// ---------------------------------------------------------------------------
// Kernel 2: [B x C] distance pass, 16 rows/block x 256 blocks (2 CTAs/SM).
// lane = row + 16*half; 16 class-groups (8 warps x 2 halves): 4x7 + 12x6 = 100.
// Fused deterministic final reduction in the last-arriving block.
// ---------------------------------------------------------------------------
__global__ void __launch_bounds__(T2, 2) k_main(const float* __restrict__ inputs,
                                                const int* __restrict__ targets,
                                                float* __restrict__ out) {
    extern __shared__ float4 dynsm[];
    float4* sx4 = dynsm;                               // [96][17] quad-major x
    float4* cls = dynsm + 96 * SXS;                    // [100][24] {WC,A} quads
    float* s_ap = reinterpret_cast<float*>(cls + NUM_C * 2 * QPC);
    float* s_an = s_ap + 8 * ROWS;
    __shared__ int s_last;
    __shared__ float s_red[8];

    const int tid = threadIdx.x;
    const int lane = tid & 31;
    const int w = tid >> 5;
    const int h = lane >> 4;
    const int row = lane & 15;
    const int row0 = blockIdx.x * ROWS;

    // Stage 16 input rows, transposed to quad-major [q][row] (coalesced LDG.128)
    {
        const float4* in4 = reinterpret_cast<const float4*>(inputs) + row0 * (NUM_D / 4);
        for (int i = tid; i < ROWS * (NUM_D / 4); i += T2) {
            const int r = i / (NUM_D / 4);
            const int q = i - r * (NUM_D / 4);
            sx4[q * SXS + r] = in4[i];
        }
    }

    const int myt = targets[row0 + row];
    const int g = h * 8 + w;                      // class group 0..15
    const int c0 = (g < 4) ? g * 7 : 28 + (g - 4) * 6;
    const int cnt = (g < 4) ? 7 : 6;

    u64 axc[7], axx[7];
    #pragma unroll
    for (int k = 0; k < 7; k++) { axc[k] = 0ull; axx[k] = 0ull; }

    const float4* __restrict__ WC4 = reinterpret_cast<const float4*>(g_WC);
    const float4* __restrict__ A4 = reinterpret_cast<const float4*>(g_A);
    const float4* myCls = cls + c0 * (2 * QPC);

    for (int s = 0; s < NCHUNKS; s++) {
        __syncthreads();   // previous chunk fully consumed (also covers x-stage)
        for (int i = tid; i < NUM_C * QPC; i += T2) {
            const int c = i / QPC;
            const int qi = i - c * QPC;
            const int src = c * (NUM_D / 4) + s * QPC + qi;
            cls[c * (2 * QPC) + 2 * qi] = WC4[src];
            cls[c * (2 * QPC) + 2 * qi + 1] = A4[src];
        }
        __syncthreads();

        const float4* sxb = sx4 + s * QPC * SXS;
        if (cnt == 7) chunk_accum<7>(sxb, myCls, row, axc, axx);
        else          chunk_accum<6>(sxb, myCls, row, axc, axx);
    }

    // Epilogue: distances + hardest pos/neg over this lane's classes
    float ap = -INFINITY, an = INFINITY;
    for (int k = 0; k < cnt; k++) {
        const int c = c0 + k;
        const float2 pc = f32x2_unpack(axc[k]);
        const float2 px = f32x2_unpack(axx[k]);
        const float d2 = g_tcc[c] - 2.f * (pc.x + pc.y) + (px.x + px.y);
        const float dist = sqrtf(fmaxf(d2, 1e-12f));
        if (c == myt) ap = fmaxf(ap, dist);
        else if (g_present[c]) an = fminf(an, dist);
    }
    // combine the two lane-halves (same row, disjoint class groups)
    ap = fmaxf(ap, __shfl_xor_sync(0xFFFFFFFFu, ap, 16));
    an = fminf(an, __shfl_xor_sync(0xFFFFFFFFu, an, 16));
    if (h == 0) {
        s_ap[w * ROWS + row] = ap;
        s_an[w * ROWS + row] = an;
    }
    __syncthreads();

    if (w == 0 && lane < 16) {
        float AP = s_ap[lane];
        float AN = s_an[lane];
        #pragma unroll
        for (int ww = 1; ww < 8; ww++) {
            AP = fmaxf(AP, s_ap[ww * ROWS + lane]);
            AN = fminf(AN, s_an[ww * ROWS + lane]);
        }
        const float cc = g_cdist[myt];
        float per = AP + fmaxf(0.f, cc - AN);
        #pragma unroll
        for (int o = 8; o; o >>= 1) per += __shfl_xor_sync(0x0000FFFFu, per, o);
        if (lane == 0) g_partial[blockIdx.x] = per;
    }

    // Fused final reduction: last-arriving block sums 256 partials in fixed order
    if (tid == 0) {
        __threadfence();
        const int old = atomicAdd(&g_count, 1);
        s_last = (old == GRID2 - 1);
    }
    __syncthreads();
    if (s_last) {
        __threadfence();                         // acquire partials
        float v = g_partial[tid];                // GRID2 == T2 == 256
        #pragma unroll
        for (int o = 16; o; o >>= 1) v += __shfl_xor_sync(0xFFFFFFFFu, v, o);
        if (lane == 0) s_red[w] = v;
        __syncthreads();
        if (tid == 0) {
            const float sum = ((s_red[0] + s_red[1]) + (s_red[2] + s_red[3]))
                            + ((s_red[4] + s_red[5]) + (s_red[6] + s_red[7]));
            out[0] = sum * (1.0f / (float)NUM_B);
            g_count = 0;                         // reset for next graph replay
        }
    }
}

// ---------------------------------------------------------------------------
extern "C" void kernel_launch(void* const* d_in, const int* in_sizes, int n_in,
                              void* d_out, int out_size) {
    (void)in_sizes; (void)n_in; (void)out_size;
    const float* inputs  = (const float*)d_in[0];   // [4096, 384] f32
    const int*   targets = (const int*)d_in[1];     // [4096] i32
    // d_in[2] = epoch_number (unused)
    const float* centers = (const float*)d_in[3];   // [100, 384] f32
    const float* cw      = (const float*)d_in[4];   // [100, 384] f32
    float* out = (float*)d_out;

    const int smem_setup = NUM_C * CEN_STRIDE * (int)sizeof(float);            // 154000
    const int smem_main = (96 * SXS + NUM_C * 2 * QPC) * (int)sizeof(float4)
                          + 2 * 8 * ROWS * (int)sizeof(float);                 // 65536
    cudaFuncSetAttribute(k_setup, cudaFuncAttributeMaxDynamicSharedMemorySize, smem_setup);
    cudaFuncSetAttribute(k_main, cudaFuncAttributeMaxDynamicSharedMemorySize, smem_main);

    k_setup<<<NUM_C, T2, smem_setup>>>(centers, cw, targets);
    k_main<<<GRID2, T2, smem_main>>>(inputs, targets, out);
}